// round 6
// baseline (speedup 1.0000x reference)
#include <cuda_runtime.h>
#include <cuda_fp16.h>
#include <math.h>

// Problem constants (fixed by the dataset)
#define N_NODES 10000
#define N_EDGES 160000
#define C_IN    64
#define C_OUT   128
#define K_TOT   125   // 5^3

// ---------------------------------------------------------------------------
// Static device scratch
// ---------------------------------------------------------------------------
__device__ __half d_acc1[(size_t)N_NODES * K_TOT * C_IN];    // 160 MB fp16
__device__ __half d_acc2[(size_t)N_NODES * K_TOT * C_OUT];   // 320 MB fp16
__device__ float  d_msg1[N_NODES * C_OUT];
__device__ float  d_msg2[N_NODES * C_OUT];
__device__ __half d_h1  [N_NODES * C_OUT];
__device__ __half d_xcat[N_NODES * 128];    // cols 0..63 = x (half); 64..127 = mean(x_src)
__device__ float  d_wcat[128 * 128];        // rows 0..63 = Wrsc; rows 64..127 = Wsc
__device__ float  d_spre[N_NODES * C_OUT];
__device__ float  d_stats[6 * 128];
// CSR scratch
__device__ int    d_cnt[N_NODES];
__device__ int    d_cur[N_NODES];
__device__ int    d_off[N_NODES + 1];
__device__ int    d_ebuf[N_EDGES];

// ---------------------------------------------------------------------------
// Helpers
// ---------------------------------------------------------------------------
__device__ __forceinline__ void red2f(float* a, float x, float y) {
    asm volatile("red.global.add.v2.f32 [%0], {%1,%2};"
                 :: "l"(a), "f"(x), "f"(y) : "memory");
}
__device__ __forceinline__ unsigned h2u(__half2 h) {
    return *reinterpret_cast<unsigned*>(&h);
}

// ---------------------------------------------------------------------------
// 0: zero the small scratch (CSR counters + stats)
// ---------------------------------------------------------------------------
__global__ void zero_small_kernel() {
    int i = blockIdx.x * blockDim.x + threadIdx.x;
    if (i < N_NODES) { d_cnt[i] = 0; d_cur[i] = 0; }
    if (i < 6 * 128) d_stats[i] = 0.f;
}

// 1: degree count
__global__ void deg_kernel(const int* __restrict__ ei) {
    int e = blockIdx.x * blockDim.x + threadIdx.x;
    if (e < N_EDGES) atomicAdd(d_cnt + ei[N_EDGES + e], 1);
}

// 2: exclusive scan of cnt -> off (single block, 1024 threads, 10 nodes each)
__global__ void __launch_bounds__(1024) scan_kernel() {
    __shared__ int ssum[1024];
    int t = threadIdx.x;
    int base = t * 10;
    int loc[10];
    int s = 0;
#pragma unroll
    for (int i = 0; i < 10; i++) {
        int n = base + i;
        int c = (n < N_NODES) ? d_cnt[n] : 0;
        loc[i] = s;
        s += c;
    }
    ssum[t] = s;
    __syncthreads();
    for (int ofs = 1; ofs < 1024; ofs <<= 1) {
        int v = 0;
        if (t >= ofs) v = ssum[t - ofs];
        __syncthreads();
        if (t >= ofs) ssum[t] += v;
        __syncthreads();
    }
    int excl = (t == 0) ? 0 : ssum[t - 1];
#pragma unroll
    for (int i = 0; i < 10; i++) {
        int n = base + i;
        if (n < N_NODES) d_off[n] = excl + loc[i];
    }
    if (t == 1023) d_off[N_NODES] = ssum[1023];
}

// 3: bucket fill
__global__ void fill_kernel(const int* __restrict__ ei) {
    int e = blockIdx.x * blockDim.x + threadIdx.x;
    if (e >= N_EDGES) return;
    int dst = ei[N_EDGES + e];
    int p = atomicAdd(d_cur + dst, 1);
    d_ebuf[d_off[dst] + p] = e;
}

// 4: prep: x -> xcat cols 0..63 (half); wcat = [Wrsc ; Wsc]
__global__ void prep_kernel(const float* __restrict__ x,
                            const float* __restrict__ Wsc,
                            const float* __restrict__ Wrsc) {
    int i = blockIdx.x * blockDim.x + threadIdx.x;
    if (i < N_NODES * 64) {
        int n = i >> 6, c = i & 63;
        d_xcat[n * 128 + c] = __float2half(x[i]);
    }
    if (i < 128 * 128) {
        int r = i >> 7;
        d_wcat[i] = (r < 64) ? Wrsc[i] : Wsc[i - 64 * 128];
    }
}

// ---------------------------------------------------------------------------
// Gather-accumulate: one CTA per dst node, blockDim = C threads (1 channel per
// thread). Tile [K_TOT][C] accumulated in fp32 smem WITHOUT atomics (edges
// serial, channels parallel). Mean fold (1/deg) applied at fp16 store.
// XAGG: also emit neighbor-mean of x into xcat cols 64..127 (conv1 only).
// ---------------------------------------------------------------------------
template <int C, bool XAGG, typename SRC>
__global__ void acc_gather_kernel(const SRC* __restrict__ src,
                                  const int* __restrict__ ei,
                                  const float* __restrict__ ea,
                                  __half* __restrict__ accout) {
    extern __shared__ float tile[];   // K_TOT * C floats
    int n = blockIdx.x;
    int c = threadIdx.x;
    for (int i = threadIdx.x; i < K_TOT * C / 4; i += C)
        ((float4*)tile)[i] = make_float4(0.f, 0.f, 0.f, 0.f);
    __syncthreads();

    int beg = d_off[n], end = d_off[n + 1];
    float xagg = 0.f;

    // 1-deep software pipeline on the src-row load
    int   e_nx = 0;
    float v_nx = 0.f;
    if (beg < end) {
        e_nx = d_ebuf[beg];
        v_nx = (float)src[(long)ei[e_nx] * C + c];
    }
    for (int i = beg; i < end; i++) {
        int e = e_nx;
        float v = v_nx;
        if (i + 1 < end) {
            e_nx = d_ebuf[i + 1];
            v_nx = (float)src[(long)ei[e_nx] * C + c];
        }
        float f0 = ea[e * 3 + 0] * 4.0f;
        float f1 = ea[e * 3 + 1] * 4.0f;
        float f2 = ea[e * 3 + 2] * 4.0f;
        float b0 = floorf(f0), b1 = floorf(f1), b2 = floorf(f2);
        float r0 = f0 - b0, r1 = f1 - b1, r2 = f2 - b2;
        int i0 = (int)b0, i1 = (int)b1, i2 = (int)b2;
        if (XAGG) xagg += v;
#pragma unroll
        for (int cor = 0; cor < 8; cor++) {
            int c0 = cor & 1, c1 = (cor >> 1) & 1, c2 = (cor >> 2) & 1;
            float w = (c0 ? r0 : 1.f - r0) * (c1 ? r1 : 1.f - r1) * (c2 ? r2 : 1.f - r2);
            int k0 = min(max(i0 + c0, 0), 4);
            int k1 = min(max(i1 + c1, 0), 4);
            int k2 = min(max(i2 + c2, 0), 4);
            int idx = (k0 * 5 + k1) * 5 + k2;
            tile[idx * C + c] += w * v;   // thread-owned column: no conflicts
        }
    }
    // no sync needed: each thread reads only its own column below
    float invd = 1.0f / fmaxf((float)(end - beg), 1.0f);
    __half* out = accout + (long)n * K_TOT * C + c;
#pragma unroll 5
    for (int k = 0; k < K_TOT; k++)
        out[k * C] = __float2half(tile[k * C + c] * invd);
    if (XAGG)
        d_xcat[n * 128 + 64 + c] = __float2half(xagg * invd);
}

// ---------------------------------------------------------------------------
// fp16 tensor-core GEMM: C[M,128] (+)= A_half[M,lda] * B_f32->h[K,128]
// BM=128 BN=128 BK=32, 256 threads (8 warps 4x2), mma.m16n8k16, ldmatrix.
// accum=1: red.v2.f32 (split-K);  accum=0: plain store.
// ---------------------------------------------------------------------------
__global__ void __launch_bounds__(256)
h16_gemm(const __half* __restrict__ A, const float* __restrict__ B,
         float* __restrict__ C, int M, int lda, int kchunk, int accum) {
    __shared__ __half As[128][40];
    __shared__ __half Bs[32][136];
    const int m0 = blockIdx.x * 128;
    const int kstart = blockIdx.z * kchunk;
    const int kend   = kstart + kchunk;
    const int tid  = threadIdx.x;
    const int warp = tid >> 5;
    const int lane = tid & 31;
    const int g = lane >> 2;
    const int t = lane & 3;
    const int wm0 = (warp >> 1) * 32;
    const int wn0 = (warp & 1) * 64;

    float c[2][8][4];
#pragma unroll
    for (int mt = 0; mt < 2; mt++)
#pragma unroll
        for (int nt = 0; nt < 8; nt++)
#pragma unroll
            for (int r = 0; r < 4; r++) c[mt][nt][r] = 0.f;

    for (int k0 = kstart; k0 < kend; k0 += 32) {
#pragma unroll
        for (int i = 0; i < 2; i++) {
            int p   = tid + i * 256;
            int row = p >> 2;
            int seg = p & 3;
            int gm  = m0 + row;
            uint4 v = make_uint4(0u, 0u, 0u, 0u);
            if (gm < M) v = *(const uint4*)(A + (long)gm * lda + k0 + seg * 8);
            *(uint2*)(&As[row][seg * 8])     = make_uint2(v.x, v.y);
            *(uint2*)(&As[row][seg * 8 + 4]) = make_uint2(v.z, v.w);
        }
#pragma unroll
        for (int i = 0; i < 4; i++) {
            int p  = tid + i * 256;
            int kk = p >> 5;
            int n4 = p & 31;
            float4 v = *(const float4*)(B + (long)(k0 + kk) * 128 + n4 * 4);
            unsigned u0 = h2u(__floats2half2_rn(v.x, v.y));
            unsigned u1 = h2u(__floats2half2_rn(v.z, v.w));
            *(uint2*)(&Bs[kk][n4 * 4]) = make_uint2(u0, u1);
        }
        __syncthreads();

#pragma unroll
        for (int ks = 0; ks < 2; ks++) {
            int kb = ks * 16;
            unsigned a[2][4];
#pragma unroll
            for (int mt = 0; mt < 2; mt++) {
                unsigned addr = (unsigned)__cvta_generic_to_shared(
                    &As[wm0 + mt * 16 + (lane & 15)][kb + (lane >> 4) * 8]);
                asm volatile("ldmatrix.sync.aligned.m8n8.x4.shared.b16 {%0,%1,%2,%3}, [%4];"
                             : "=r"(a[mt][0]), "=r"(a[mt][1]), "=r"(a[mt][2]), "=r"(a[mt][3])
                             : "r"(addr));
            }
            unsigned b[8][2];
#pragma unroll
            for (int nt2 = 0; nt2 < 4; nt2++) {
                unsigned addr = (unsigned)__cvta_generic_to_shared(
                    &Bs[kb + (lane & 15)][wn0 + nt2 * 16 + (lane >> 4) * 8]);
                asm volatile("ldmatrix.sync.aligned.m8n8.x4.trans.shared.b16 {%0,%1,%2,%3}, [%4];"
                             : "=r"(b[nt2 * 2][0]), "=r"(b[nt2 * 2][1]),
                               "=r"(b[nt2 * 2 + 1][0]), "=r"(b[nt2 * 2 + 1][1])
                             : "r"(addr));
            }
#pragma unroll
            for (int nt = 0; nt < 8; nt++)
#pragma unroll
                for (int mt = 0; mt < 2; mt++) {
                    asm volatile(
                        "mma.sync.aligned.m16n8k16.row.col.f32.f16.f16.f32 "
                        "{%0,%1,%2,%3}, {%4,%5,%6,%7}, {%8,%9}, {%0,%1,%2,%3};"
                        : "+f"(c[mt][nt][0]), "+f"(c[mt][nt][1]),
                          "+f"(c[mt][nt][2]), "+f"(c[mt][nt][3])
                        : "r"(a[mt][0]), "r"(a[mt][1]), "r"(a[mt][2]), "r"(a[mt][3]),
                          "r"(b[nt][0]), "r"(b[nt][1]));
                }
        }
        __syncthreads();
    }

#pragma unroll
    for (int mt = 0; mt < 2; mt++)
#pragma unroll
        for (int nt = 0; nt < 8; nt++) {
            int row = m0 + wm0 + mt * 16 + g;
            int col = wn0 + nt * 8 + 2 * t;
            if (accum) {
                if (row < M)
                    red2f(C + (long)row * 128 + col, c[mt][nt][0], c[mt][nt][1]);
                if (row + 8 < M)
                    red2f(C + (long)(row + 8) * 128 + col, c[mt][nt][2], c[mt][nt][3]);
            } else {
                if (row < M)
                    *(float2*)(C + (long)row * 128 + col) =
                        make_float2(c[mt][nt][0], c[mt][nt][1]);
                if (row + 8 < M)
                    *(float2*)(C + (long)(row + 8) * 128 + col) =
                        make_float2(c[mt][nt][2], c[mt][nt][3]);
            }
        }
}

// ---------------------------------------------------------------------------
// BN column stats
// ---------------------------------------------------------------------------
__global__ void bn_stats_kernel(const float* __restrict__ y, float* __restrict__ st) {
    int c = threadIdx.x;
    int r0 = blockIdx.x * 100;
    float s = 0.f, s2 = 0.f;
    for (int r = 0; r < 100; r++) {
        float v = y[(long)(r0 + r) * 128 + c];
        s += v; s2 += v * v;
    }
    atomicAdd(&st[c], s);
    atomicAdd(&st[128 + c], s2);
}

__global__ void bn_stats2_kernel(const float* __restrict__ ya, const float* __restrict__ yb,
                                 float* __restrict__ sta, float* __restrict__ stb) {
    int c = threadIdx.x;
    int r0 = blockIdx.x * 100;
    float s = 0.f, s2 = 0.f, u = 0.f, u2 = 0.f;
    for (int r = 0; r < 100; r++) {
        float v = ya[(long)(r0 + r) * 128 + c];
        s += v; s2 += v * v;
        float w = yb[(long)(r0 + r) * 128 + c];
        u += w; u2 += w * w;
    }
    atomicAdd(&sta[c], s);
    atomicAdd(&sta[128 + c], s2);
    atomicAdd(&stb[c], u);
    atomicAdd(&stb[128 + c], u2);
}

// ---------------------------------------------------------------------------
// bn + elu -> h1 (fp16)
// ---------------------------------------------------------------------------
__global__ void bn_elu_kernel(const float* __restrict__ y, const float* __restrict__ st,
                              const float* __restrict__ gg, const float* __restrict__ bb,
                              __half* __restrict__ outp) {
    int idx = blockIdx.x * blockDim.x + threadIdx.x;
    int c = idx & 127;
    float mean = st[c] * (1.0f / N_NODES);
    float var  = st[128 + c] * (1.0f / N_NODES) - mean * mean;
    float rs   = rsqrtf(var + 1e-5f);
    float v = (y[idx] - mean) * rs * gg[c] + bb[c];
    outp[idx] = __float2half(v > 0.f ? v : expm1f(v));
}

// ---------------------------------------------------------------------------
// final: elu(bn(conv2) + bn(shortcut))
// ---------------------------------------------------------------------------
__global__ void final_kernel(const float* __restrict__ st2, const float* __restrict__ sts,
                             const float* __restrict__ g2, const float* __restrict__ be2,
                             const float* __restrict__ gsc, const float* __restrict__ besc,
                             float* __restrict__ outp) {
    int idx = blockIdx.x * blockDim.x + threadIdx.x;
    int c = idx & 127;
    float m2 = st2[c] * (1.0f / N_NODES);
    float v2 = st2[128 + c] * (1.0f / N_NODES) - m2 * m2;
    float a  = (d_msg2[idx] - m2) * rsqrtf(v2 + 1e-5f) * g2[c] + be2[c];
    float ms = sts[c] * (1.0f / N_NODES);
    float vs = sts[128 + c] * (1.0f / N_NODES) - ms * ms;
    float b  = (d_spre[idx] - ms) * rsqrtf(vs + 1e-5f) * gsc[c] + besc[c];
    float v = a + b;
    outp[idx] = v > 0.f ? v : expm1f(v);
}

// ---------------------------------------------------------------------------
// Launch (#5 = acc1 gather for ncu)
// ---------------------------------------------------------------------------
extern "C" void kernel_launch(void* const* d_in, const int* in_sizes, int n_in,
                              void* d_out, int out_size) {
    const float* x    = (const float*)d_in[0];
    const int*   ei   = (const int*)  d_in[1];
    const float* ea   = (const float*)d_in[2];
    const float* W1   = (const float*)d_in[3];
    const float* Wr1  = (const float*)d_in[4];
    const float* g1   = (const float*)d_in[6];
    const float* be1  = (const float*)d_in[7];
    const float* W2   = (const float*)d_in[8];
    const float* Wr2  = (const float*)d_in[9];
    const float* g2   = (const float*)d_in[11];
    const float* be2  = (const float*)d_in[12];
    const float* Wsc  = (const float*)d_in[13];
    const float* Wrsc = (const float*)d_in[14];
    const float* gsc  = (const float*)d_in[16];
    const float* besc = (const float*)d_in[17];
    float* out = (float*)d_out;

    __half *acc1, *acc2, *h1, *xcat;
    float *msg1, *msg2, *spre, *stats, *wcat;
    cudaGetSymbolAddress((void**)&acc1,  d_acc1);
    cudaGetSymbolAddress((void**)&acc2,  d_acc2);
    cudaGetSymbolAddress((void**)&h1,    d_h1);
    cudaGetSymbolAddress((void**)&xcat,  d_xcat);
    cudaGetSymbolAddress((void**)&msg1,  d_msg1);
    cudaGetSymbolAddress((void**)&msg2,  d_msg2);
    cudaGetSymbolAddress((void**)&spre,  d_spre);
    cudaGetSymbolAddress((void**)&stats, d_stats);
    cudaGetSymbolAddress((void**)&wcat,  d_wcat);

    // raise dynamic smem limit for the conv2 gather tile (64 KB)
    static bool attr_done = false;
    if (!attr_done) {
        cudaFuncSetAttribute(acc_gather_kernel<C_IN, true, float>,
                             cudaFuncAttributeMaxDynamicSharedMemorySize,
                             K_TOT * C_IN * 4);
        cudaFuncSetAttribute(acc_gather_kernel<C_OUT, false, __half>,
                             cudaFuncAttributeMaxDynamicSharedMemorySize,
                             K_TOT * C_OUT * 4);
        attr_done = true;
    }

    const int GB = (N_NODES + 127) / 128;

    // 0: zero small scratch
    zero_small_kernel<<<(N_NODES + 255) / 256, 256>>>();
    // 1: degree count
    deg_kernel<<<(N_EDGES + 255) / 256, 256>>>(ei);
    // 2: offsets scan
    scan_kernel<<<1, 1024>>>();
    // 3: bucket fill
    fill_kernel<<<(N_EDGES + 255) / 256, 256>>>(ei);
    // 4: prep (x->half, wcat)
    prep_kernel<<<(N_NODES * 64 + 255) / 256, 256>>>(x, Wsc, Wrsc);
    // 5: conv1 gather-accumulate -> acc1 (+ xcat neighbor mean)
    acc_gather_kernel<C_IN, true, float>
        <<<N_NODES, C_IN, K_TOT * C_IN * 4>>>(x, ei, ea, acc1);
    // 6: root1 GEMM (store): xcat[:, :64] @ Wr1 -> msg1
    h16_gemm<<<dim3(GB, 1, 1), 256>>>(xcat, Wr1, msg1, N_NODES, 128, 64, 0);
    // 7: conv1 GEMM (red, split-K 10) -> msg1
    h16_gemm<<<dim3(GB, 1, 10), 256>>>(acc1, W1, msg1, N_NODES, K_TOT * C_IN, 800, 1);
    // 8: bn1 stats
    bn_stats_kernel<<<100, 128>>>(msg1, stats);
    // 9: bn1 + elu -> h1
    bn_elu_kernel<<<(N_NODES * C_OUT) / 512, 512>>>(msg1, stats, g1, be1, h1);
    // 10: conv2 gather-accumulate -> acc2
    acc_gather_kernel<C_OUT, false, __half>
        <<<N_NODES, C_OUT, K_TOT * C_OUT * 4>>>(h1, ei, ea, acc2);
    // 11: root2 GEMM (store): h1 @ Wr2 -> msg2
    h16_gemm<<<dim3(GB, 1, 1), 256>>>(h1, Wr2, msg2, N_NODES, 128, 128, 0);
    // 12: conv2 GEMM (red, split-K 10) -> msg2
    h16_gemm<<<dim3(GB, 1, 10), 256>>>(acc2, W2, msg2, N_NODES, K_TOT * C_OUT, 1600, 1);
    // 13: shortcut GEMM (store): xcat @ wcat -> spre
    h16_gemm<<<dim3(GB, 1, 1), 256>>>(xcat, wcat, spre, N_NODES, 128, 128, 0);
    // 14: bn2 + bnS stats
    bn_stats2_kernel<<<100, 128>>>(msg2, spre, stats + 256, stats + 512);
    // 15: final
    final_kernel<<<(N_NODES * C_OUT) / 512, 512>>>(stats + 256, stats + 512,
                                                   g2, be2, gsc, besc, out);
}

// round 15
// speedup vs baseline: 1.5112x; 1.5112x over previous
#include <cuda_runtime.h>
#include <cuda_fp16.h>
#include <math.h>

// Problem constants (fixed by the dataset)
#define N_NODES 10000
#define N_EDGES 160000
#define C_IN    64
#define C_OUT   128
#define K_TOT   125   // 5^3

// ---------------------------------------------------------------------------
// Static device scratch
// ---------------------------------------------------------------------------
__device__ __half d_acc1[(size_t)N_NODES * K_TOT * C_IN];    // 160 MB fp16
__device__ __half d_acc2[(size_t)N_NODES * K_TOT * C_OUT];   // 320 MB fp16
__device__ float  d_msg1[N_NODES * C_OUT];
__device__ float  d_msg2[N_NODES * C_OUT];
__device__ __half d_h1  [N_NODES * C_OUT];
__device__ __half d_xcat[N_NODES * 128];    // cols 0..63 = x (half); 64..127 = mean(x_src)
__device__ float  d_spre[N_NODES * C_OUT];
__device__ float  d_deg [N_NODES];
__device__ float  d_stats[6 * 128];
// fp16 weight copies
__device__ __half d_w1h [K_TOT * C_IN * C_OUT];     // 1,024,000
__device__ __half d_w2h [K_TOT * C_OUT * C_OUT];    // 2,048,000
__device__ __half d_wr1h[C_IN * C_OUT];             // 8,192
__device__ __half d_wr2h[C_OUT * C_OUT];            // 16,384
__device__ __half d_wcath[128 * 128];               // rows 0..63 Wrsc; 64..127 Wsc

// ---------------------------------------------------------------------------
// Helpers
// ---------------------------------------------------------------------------
__device__ __forceinline__ void red2f(float* a, float x, float y) {
    asm volatile("red.global.add.v2.f32 [%0], {%1,%2};"
                 :: "l"(a), "f"(x), "f"(y) : "memory");
}
__device__ __forceinline__ void red16h(__half* a, unsigned h0, unsigned h1,
                                       unsigned h2, unsigned h3) {
    asm volatile("red.global.add.noftz.v4.f16x2 [%0], {%1,%2,%3,%4};"
                 :: "l"(a), "r"(h0), "r"(h1), "r"(h2), "r"(h3) : "memory");
}
__device__ __forceinline__ unsigned h2u(__half2 h) {
    return *reinterpret_cast<unsigned*>(&h);
}
__device__ __forceinline__ void cp16(void* smem_dst, const void* gsrc, int src_bytes) {
    unsigned s = (unsigned)__cvta_generic_to_shared(smem_dst);
    asm volatile("cp.async.ca.shared.global [%0], [%1], 16, %2;"
                 :: "r"(s), "l"(gsrc), "r"(src_bytes));
}
#define CP_COMMIT() asm volatile("cp.async.commit_group;")
#define CP_WAIT0()  asm volatile("cp.async.wait_group 0;")

// ---------------------------------------------------------------------------
// Zero scratch that must start at 0 (acc1, acc2, xcat, deg, stats)
// ---------------------------------------------------------------------------
#define U4_ACC1 ((long)N_NODES * K_TOT * C_IN / 8)
#define U4_ACC2 ((long)N_NODES * K_TOT * C_OUT / 8)
#define U4_XCAT ((long)N_NODES * 128 / 8)
#define U4_DEG  ((long)N_NODES / 4)
#define U4_ST   (6 * 128 / 4)
#define U4_TOTAL (U4_ACC1 + U4_ACC2 + U4_XCAT + U4_DEG + U4_ST)

__global__ void zero_all_kernel() {
    long i = (long)blockIdx.x * blockDim.x + threadIdx.x;
    if (i >= U4_TOTAL) return;
    uint4 z = make_uint4(0u, 0u, 0u, 0u);
    if (i < U4_ACC1) { ((uint4*)d_acc1)[i] = z; return; }
    i -= U4_ACC1;
    if (i < U4_ACC2) { ((uint4*)d_acc2)[i] = z; return; }
    i -= U4_ACC2;
    if (i < U4_XCAT) { ((uint4*)d_xcat)[i] = z; return; }
    i -= U4_XCAT;
    if (i < U4_DEG) { ((uint4*)d_deg)[i] = z; return; }
    i -= U4_DEG;
    ((uint4*)d_stats)[i] = z;
}

// ---------------------------------------------------------------------------
// Degree count
// ---------------------------------------------------------------------------
__global__ void deg_kernel(const int* __restrict__ ei) {
    int e = blockIdx.x * blockDim.x + threadIdx.x;
    if (e < N_EDGES) atomicAdd(d_deg + ei[N_EDGES + e], 1.0f);
}

// ---------------------------------------------------------------------------
// Prep: x -> xcat cols 0..63 (half); all weights -> fp16
// ---------------------------------------------------------------------------
#define P_X    (N_NODES * 64)
#define P_W1   (K_TOT * C_IN * C_OUT)
#define P_W2   (K_TOT * C_OUT * C_OUT)
#define P_WR1  (C_IN * C_OUT)
#define P_WR2  (C_OUT * C_OUT)
#define P_WCAT (128 * 128)
#define P_TOTAL (P_X + P_W1 + P_W2 + P_WR1 + P_WR2 + P_WCAT)

__global__ void prep_kernel(const float* __restrict__ x,
                            const float* __restrict__ W1,
                            const float* __restrict__ W2,
                            const float* __restrict__ Wr1,
                            const float* __restrict__ Wr2,
                            const float* __restrict__ Wsc,
                            const float* __restrict__ Wrsc) {
    long i = (long)blockIdx.x * blockDim.x + threadIdx.x;
    if (i >= P_TOTAL) return;
    if (i < P_X) {
        int n = (int)(i >> 6), c = (int)(i & 63);
        d_xcat[n * 128 + c] = __float2half(x[i]);
        return;
    }
    i -= P_X;
    if (i < P_W1) { d_w1h[i] = __float2half(W1[i]); return; }
    i -= P_W1;
    if (i < P_W2) { d_w2h[i] = __float2half(W2[i]); return; }
    i -= P_W2;
    if (i < P_WR1) { d_wr1h[i] = __float2half(Wr1[i]); return; }
    i -= P_WR1;
    if (i < P_WR2) { d_wr2h[i] = __float2half(Wr2[i]); return; }
    i -= P_WR2;
    {
        int r = (int)(i >> 7);
        d_wcath[i] = __float2half((r < 64) ? Wrsc[i] : Wsc[i - 64 * 128]);
    }
}

// ---------------------------------------------------------------------------
// Spline basis helpers
// ---------------------------------------------------------------------------
__device__ __forceinline__ void spline_cell(const float* __restrict__ ea, int e,
                                            float f[3], int ib[3]) {
#pragma unroll
    for (int d = 0; d < 3; d++) {
        float v = ea[e * 3 + d] * 4.0f;
        float b = floorf(v);
        f[d] = v - b;
        ib[d] = (int)b;
    }
}
__device__ __forceinline__ int corner_idx_w(const float f[3], const int ib[3],
                                            int c, float& w) {
    int b0 = c & 1, b1 = (c >> 1) & 1, b2 = (c >> 2) & 1;
    w = (b0 ? f[0] : 1.f - f[0]) * (b1 ? f[1] : 1.f - f[1]) * (b2 ? f[2] : 1.f - f[2]);
    int k0 = min(max(ib[0] + b0, 0), 4);
    int k1 = min(max(ib[1] + b1, 0), 4);
    int k2 = min(max(ib[2] + b2, 0), 4);
    return (k0 * 5 + k1) * 5 + k2;
}

// ---------------------------------------------------------------------------
// Scatter conv1 (R5-verified): acc1 += (w/deg)*x_src; xcat[64:] += x_src/deg
// ---------------------------------------------------------------------------
__global__ void scatter1_kernel(const float* __restrict__ xf, const int* __restrict__ ei,
                                const float* __restrict__ ea) {
    int lane = threadIdx.x & 7;
    int g    = threadIdx.x >> 3;
    int e    = blockIdx.x * 16 + g;
    int src = ei[e];
    int dst = ei[N_EDGES + e];
    float invd = 1.0f / fmaxf(d_deg[dst], 1.0f);
    float f[3]; int ib[3];
    spline_cell(ea, e, f, ib);
    const float4* xr = (const float4*)(xf + (long)src * C_IN);
    float4 v0 = xr[lane * 2];
    float4 v1 = xr[lane * 2 + 1];
    v0.x *= invd; v0.y *= invd; v0.z *= invd; v0.w *= invd;
    v1.x *= invd; v1.y *= invd; v1.z *= invd; v1.w *= invd;
#pragma unroll
    for (int c = 0; c < 8; c++) {
        float w; int idx = corner_idx_w(f, ib, c, w);
        unsigned h0 = h2u(__floats2half2_rn(w * v0.x, w * v0.y));
        unsigned h1 = h2u(__floats2half2_rn(w * v0.z, w * v0.w));
        unsigned h2 = h2u(__floats2half2_rn(w * v1.x, w * v1.y));
        unsigned h3 = h2u(__floats2half2_rn(w * v1.z, w * v1.w));
        red16h(d_acc1 + ((long)dst * K_TOT + idx) * C_IN + lane * 8, h0, h1, h2, h3);
    }
    unsigned s0 = h2u(__floats2half2_rn(v0.x, v0.y));
    unsigned s1 = h2u(__floats2half2_rn(v0.z, v0.w));
    unsigned s2 = h2u(__floats2half2_rn(v1.x, v1.y));
    unsigned s3 = h2u(__floats2half2_rn(v1.z, v1.w));
    red16h(d_xcat + (long)dst * 128 + 64 + lane * 8, s0, s1, s2, s3);
}

// ---------------------------------------------------------------------------
// Scatter conv2 (R5-verified): acc2 += (w/deg)*h1_src
// ---------------------------------------------------------------------------
__global__ void scatter2_kernel(const int* __restrict__ ei, const float* __restrict__ ea) {
    int lane = threadIdx.x & 15;
    int g    = threadIdx.x >> 4;
    int e    = blockIdx.x * 8 + g;
    int src = ei[e];
    int dst = ei[N_EDGES + e];
    float invd = 1.0f / fmaxf(d_deg[dst], 1.0f);
    float f[3]; int ib[3];
    spline_cell(ea, e, f, ib);
    uint4 hv = __ldg((const uint4*)(d_h1 + (long)src * C_OUT + lane * 8));
    float2 p0 = __half22float2(*reinterpret_cast<__half2*>(&hv.x));
    float2 p1 = __half22float2(*reinterpret_cast<__half2*>(&hv.y));
    float2 p2 = __half22float2(*reinterpret_cast<__half2*>(&hv.z));
    float2 p3 = __half22float2(*reinterpret_cast<__half2*>(&hv.w));
#pragma unroll
    for (int c = 0; c < 8; c++) {
        float w; int idx = corner_idx_w(f, ib, c, w);
        float ws = w * invd;
        unsigned h0 = h2u(__floats2half2_rn(ws * p0.x, ws * p0.y));
        unsigned h1 = h2u(__floats2half2_rn(ws * p1.x, ws * p1.y));
        unsigned h2 = h2u(__floats2half2_rn(ws * p2.x, ws * p2.y));
        unsigned h3 = h2u(__floats2half2_rn(ws * p3.x, ws * p3.y));
        red16h(d_acc2 + ((long)dst * K_TOT + idx) * C_OUT + lane * 8, h0, h1, h2, h3);
    }
}

// ---------------------------------------------------------------------------
// fp16 tensor-core GEMM, 2-stage cp.async double-buffered.
// C[M,128] (+)= A_half[M,lda] * B_half[K,128]
// BM=128 BN=128 BK=32, 256 threads (8 warps 4x2), mma.m16n8k16, ldmatrix.
// accum=1: red.v2.f32 (split-K); accum=0: plain store.
// ---------------------------------------------------------------------------
__global__ void __launch_bounds__(256)
h16_gemm(const __half* __restrict__ A, const __half* __restrict__ B,
         float* __restrict__ C, int M, int lda, int kchunk, int accum) {
    __shared__ __half As[2][128][40];
    __shared__ __half Bs[2][32][136];
    const int m0 = blockIdx.x * 128;
    const int kstart = blockIdx.z * kchunk;
    const int niter  = kchunk >> 5;
    const int tid  = threadIdx.x;
    const int warp = tid >> 5;
    const int lane = tid & 31;
    const int g = lane >> 2;
    const int t = lane & 3;
    const int wm0 = (warp >> 1) * 32;
    const int wn0 = (warp & 1) * 64;

    // per-thread load coords
    const int arow = tid >> 2;          // 0..63 (+64 for second chunk)
    const int aseg = tid & 3;
    const int bkk  = tid >> 4;          // 0..15 (+16)
    const int bn8  = tid & 15;

    float c[2][8][4];
#pragma unroll
    for (int mt = 0; mt < 2; mt++)
#pragma unroll
        for (int nt = 0; nt < 8; nt++)
#pragma unroll
            for (int r = 0; r < 4; r++) c[mt][nt][r] = 0.f;

    // stage loader (zfill-guard: clamp OOB rows to row 0, copy 0 bytes)
    auto load_stage = [&](int s, int k0) {
#pragma unroll
        for (int i = 0; i < 2; i++) {
            int row = arow + i * 64;
            int gm  = m0 + row;
            int ok  = (gm < M);
            long arowoff = ok ? (long)gm * lda : 0;
            cp16(&As[s][row][aseg * 8],
                 A + arowoff + k0 + aseg * 8,
                 ok ? 16 : 0);
        }
#pragma unroll
        for (int i = 0; i < 2; i++) {
            int kk = bkk + i * 16;
            cp16(&Bs[s][kk][bn8 * 8],
                 B + (long)(k0 + kk) * 128 + bn8 * 8, 16);
        }
    };

    load_stage(0, kstart);
    CP_COMMIT();

    for (int it = 0; it < niter; it++) {
        int cur = it & 1;
        CP_WAIT0();
        __syncthreads();
        if (it + 1 < niter) {
            load_stage(cur ^ 1, kstart + (it + 1) * 32);
            CP_COMMIT();
        }

#pragma unroll
        for (int ks = 0; ks < 2; ks++) {
            int kb = ks * 16;
            unsigned a[2][4];
#pragma unroll
            for (int mt = 0; mt < 2; mt++) {
                unsigned addr = (unsigned)__cvta_generic_to_shared(
                    &As[cur][wm0 + mt * 16 + (lane & 15)][kb + (lane >> 4) * 8]);
                asm volatile("ldmatrix.sync.aligned.m8n8.x4.shared.b16 {%0,%1,%2,%3}, [%4];"
                             : "=r"(a[mt][0]), "=r"(a[mt][1]), "=r"(a[mt][2]), "=r"(a[mt][3])
                             : "r"(addr));
            }
            unsigned b[8][2];
#pragma unroll
            for (int nt2 = 0; nt2 < 4; nt2++) {
                unsigned addr = (unsigned)__cvta_generic_to_shared(
                    &Bs[cur][kb + (lane & 15)][wn0 + nt2 * 16 + (lane >> 4) * 8]);
                asm volatile("ldmatrix.sync.aligned.m8n8.x4.trans.shared.b16 {%0,%1,%2,%3}, [%4];"
                             : "=r"(b[nt2 * 2][0]), "=r"(b[nt2 * 2][1]),
                               "=r"(b[nt2 * 2 + 1][0]), "=r"(b[nt2 * 2 + 1][1])
                             : "r"(addr));
            }
#pragma unroll
            for (int nt = 0; nt < 8; nt++)
#pragma unroll
                for (int mt = 0; mt < 2; mt++) {
                    asm volatile(
                        "mma.sync.aligned.m16n8k16.row.col.f32.f16.f16.f32 "
                        "{%0,%1,%2,%3}, {%4,%5,%6,%7}, {%8,%9}, {%0,%1,%2,%3};"
                        : "+f"(c[mt][nt][0]), "+f"(c[mt][nt][1]),
                          "+f"(c[mt][nt][2]), "+f"(c[mt][nt][3])
                        : "r"(a[mt][0]), "r"(a[mt][1]), "r"(a[mt][2]), "r"(a[mt][3]),
                          "r"(b[nt][0]), "r"(b[nt][1]));
                }
        }
        __syncthreads();
    }

#pragma unroll
    for (int mt = 0; mt < 2; mt++)
#pragma unroll
        for (int nt = 0; nt < 8; nt++) {
            int row = m0 + wm0 + mt * 16 + g;
            int col = wn0 + nt * 8 + 2 * t;
            if (accum) {
                if (row < M)
                    red2f(C + (long)row * 128 + col, c[mt][nt][0], c[mt][nt][1]);
                if (row + 8 < M)
                    red2f(C + (long)(row + 8) * 128 + col, c[mt][nt][2], c[mt][nt][3]);
            } else {
                if (row < M)
                    *(float2*)(C + (long)row * 128 + col) =
                        make_float2(c[mt][nt][0], c[mt][nt][1]);
                if (row + 8 < M)
                    *(float2*)(C + (long)(row + 8) * 128 + col) =
                        make_float2(c[mt][nt][2], c[mt][nt][3]);
            }
        }
}

// ---------------------------------------------------------------------------
// BN column stats
// ---------------------------------------------------------------------------
__global__ void bn_stats_kernel(const float* __restrict__ y, float* __restrict__ st) {
    int c = threadIdx.x;
    int r0 = blockIdx.x * 100;
    float s = 0.f, s2 = 0.f;
    for (int r = 0; r < 100; r++) {
        float v = y[(long)(r0 + r) * 128 + c];
        s += v; s2 += v * v;
    }
    atomicAdd(&st[c], s);
    atomicAdd(&st[128 + c], s2);
}

__global__ void bn_stats2_kernel(const float* __restrict__ ya, const float* __restrict__ yb,
                                 float* __restrict__ sta, float* __restrict__ stb) {
    int c = threadIdx.x;
    int r0 = blockIdx.x * 100;
    float s = 0.f, s2 = 0.f, u = 0.f, u2 = 0.f;
    for (int r = 0; r < 100; r++) {
        float v = ya[(long)(r0 + r) * 128 + c];
        s += v; s2 += v * v;
        float w = yb[(long)(r0 + r) * 128 + c];
        u += w; u2 += w * w;
    }
    atomicAdd(&sta[c], s);
    atomicAdd(&sta[128 + c], s2);
    atomicAdd(&stb[c], u);
    atomicAdd(&stb[128 + c], u2);
}

// ---------------------------------------------------------------------------
// bn + elu -> h1 (fp16)
// ---------------------------------------------------------------------------
__global__ void bn_elu_kernel(const float* __restrict__ y, const float* __restrict__ st,
                              const float* __restrict__ gg, const float* __restrict__ bb,
                              __half* __restrict__ outp) {
    int idx = blockIdx.x * blockDim.x + threadIdx.x;
    int c = idx & 127;
    float mean = st[c] * (1.0f / N_NODES);
    float var  = st[128 + c] * (1.0f / N_NODES) - mean * mean;
    float rs   = rsqrtf(var + 1e-5f);
    float v = (y[idx] - mean) * rs * gg[c] + bb[c];
    outp[idx] = __float2half(v > 0.f ? v : expm1f(v));
}

// ---------------------------------------------------------------------------
// final: elu(bn(conv2) + bn(shortcut))
// ---------------------------------------------------------------------------
__global__ void final_kernel(const float* __restrict__ st2, const float* __restrict__ sts,
                             const float* __restrict__ g2, const float* __restrict__ be2,
                             const float* __restrict__ gsc, const float* __restrict__ besc,
                             float* __restrict__ outp) {
    int idx = blockIdx.x * blockDim.x + threadIdx.x;
    int c = idx & 127;
    float m2 = st2[c] * (1.0f / N_NODES);
    float v2 = st2[128 + c] * (1.0f / N_NODES) - m2 * m2;
    float a  = (d_msg2[idx] - m2) * rsqrtf(v2 + 1e-5f) * g2[c] + be2[c];
    float ms = sts[c] * (1.0f / N_NODES);
    float vs = sts[128 + c] * (1.0f / N_NODES) - ms * ms;
    float b  = (d_spre[idx] - ms) * rsqrtf(vs + 1e-5f) * gsc[c] + besc[c];
    float v = a + b;
    outp[idx] = v > 0.f ? v : expm1f(v);
}

// ---------------------------------------------------------------------------
// Launch
// ---------------------------------------------------------------------------
extern "C" void kernel_launch(void* const* d_in, const int* in_sizes, int n_in,
                              void* d_out, int out_size) {
    const float* x    = (const float*)d_in[0];
    const int*   ei   = (const int*)  d_in[1];
    const float* ea   = (const float*)d_in[2];
    const float* W1   = (const float*)d_in[3];
    const float* Wr1  = (const float*)d_in[4];
    const float* g1   = (const float*)d_in[6];
    const float* be1  = (const float*)d_in[7];
    const float* W2   = (const float*)d_in[8];
    const float* Wr2  = (const float*)d_in[9];
    const float* g2   = (const float*)d_in[11];
    const float* be2  = (const float*)d_in[12];
    const float* Wsc  = (const float*)d_in[13];
    const float* Wrsc = (const float*)d_in[14];
    const float* gsc  = (const float*)d_in[16];
    const float* besc = (const float*)d_in[17];
    float* out = (float*)d_out;

    __half *acc1, *acc2, *h1, *xcat, *w1h, *w2h, *wr1h, *wr2h, *wcath;
    float *msg1, *msg2, *spre, *stats;
    cudaGetSymbolAddress((void**)&acc1,  d_acc1);
    cudaGetSymbolAddress((void**)&acc2,  d_acc2);
    cudaGetSymbolAddress((void**)&h1,    d_h1);
    cudaGetSymbolAddress((void**)&xcat,  d_xcat);
    cudaGetSymbolAddress((void**)&msg1,  d_msg1);
    cudaGetSymbolAddress((void**)&msg2,  d_msg2);
    cudaGetSymbolAddress((void**)&spre,  d_spre);
    cudaGetSymbolAddress((void**)&stats, d_stats);
    cudaGetSymbolAddress((void**)&w1h,   d_w1h);
    cudaGetSymbolAddress((void**)&w2h,   d_w2h);
    cudaGetSymbolAddress((void**)&wr1h,  d_wr1h);
    cudaGetSymbolAddress((void**)&wr2h,  d_wr2h);
    cudaGetSymbolAddress((void**)&wcath, d_wcath);

    const int GB = (N_NODES + 127) / 128;

    // 0: zero (acc1, acc2, xcat, deg, stats)
    zero_all_kernel<<<(unsigned)((U4_TOTAL + 255) / 256), 256>>>();
    // 1: degree count
    deg_kernel<<<(N_EDGES + 255) / 256, 256>>>(ei);
    // 2: prep (x->half, all weights->half)
    prep_kernel<<<(unsigned)((P_TOTAL + 255) / 256), 256>>>(x, W1, W2, Wr1, Wr2, Wsc, Wrsc);
    // 3: conv1 scatter (mean-folded; xcat neighbor mean)
    scatter1_kernel<<<N_EDGES / 16, 128>>>(x, ei, ea);
    // 4: root1 GEMM (store): xcat[:, :64] @ Wr1 -> msg1
    h16_gemm<<<dim3(GB, 1, 1), 256>>>(xcat, wr1h, msg1, N_NODES, 128, 64, 0);
    // 5: conv1 GEMM (red, split-K 10)
    h16_gemm<<<dim3(GB, 1, 10), 256>>>(acc1, w1h, msg1, N_NODES, K_TOT * C_IN, 800, 1);
    // 6: bn1 stats
    bn_stats_kernel<<<100, 128>>>(msg1, stats);
    // 7: bn1 + elu -> h1
    bn_elu_kernel<<<(N_NODES * C_OUT) / 512, 512>>>(msg1, stats, g1, be1, h1);
    // 8: conv2 scatter
    scatter2_kernel<<<N_EDGES / 8, 128>>>(ei, ea);
    // 9: root2 GEMM (store): h1 @ Wr2 -> msg2
    h16_gemm<<<dim3(GB, 1, 1), 256>>>(h1, wr2h, msg2, N_NODES, 128, 128, 0);
    // 10: conv2 GEMM (red, split-K 10)
    h16_gemm<<<dim3(GB, 1, 10), 256>>>(acc2, w2h, msg2, N_NODES, K_TOT * C_OUT, 1600, 1);
    // 11: shortcut GEMM (store): xcat @ wcat -> spre
    h16_gemm<<<dim3(GB, 1, 1), 256>>>(xcat, wcath, spre, N_NODES, 128, 128, 0);
    // 12: bn2 + bnS stats
    bn_stats2_kernel<<<100, 128>>>(msg2, spre, stats + 256, stats + 512);
    // 13: final
    final_kernel<<<(N_NODES * C_OUT) / 512, 512>>>(stats + 256, stats + 512,
                                                   g2, be2, gsc, besc, out);
}